// round 14
// baseline (speedup 1.0000x reference)
#include <cuda_runtime.h>
#include <math.h>

// KarplusStrongResonator: (1 + q) Y = X, q = a1 z^-d1 + a2 z^-d2,
// d1 = 61 + argmax(delay_param + gumbel), d2 = 61 + ((argmax+1) % 360).
// Triple doubling: (1 - q^8) Y = (1-q)(1+q^2)(1+q^4) X.
// Fast path (d2 == d1+1): every q^k has a contiguous tap window, all passes
// vectorized as aligned float4 reads (alignment handled by template switch).
// Recurrence runs on a named barrier among only the warps that have work.

#define T_LEN 8192
#define B_ROWS 128
#define NDELAY 360
#define NT 512
#define NWARP (NT / 32)
#define PAD 3360   // == 8 * 420 (max lag), multiple of 4

__device__ __forceinline__ float4 lds4(const float* p) {
    return *reinterpret_cast<const float4*>(p);
}

// pass A: B[t] = A[t] - a1*A[t-d1] - a2*A[t-d1-1]. M = alignment fixup so
// (d1+1+M) % 4 == 0; window W[M+s..M+s+1] = A[t-d1-1 .. t-d1].
template<int M>
__device__ __forceinline__ void pass_a_vec(const float* __restrict__ A,
                                           float* __restrict__ B,
                                           float a1, float a2, int d1,
                                           int t_begin, int t_end, int tid)
{
    const int off = d1 + 1 + M;          // aligned distance below t0
    for (int t0 = t_begin + 4 * tid; t0 < t_end; t0 += 4 * NT) {
        float4 c  = lds4(&A[t0]);
        float4 w0 = lds4(&A[t0 - off]);
        float4 w1 = lds4(&A[t0 - off + 4]);
        float W[8] = {w0.x, w0.y, w0.z, w0.w, w1.x, w1.y, w1.z, w1.w};
        float cv[4] = {c.x, c.y, c.z, c.w};
        float r[4];
        #pragma unroll
        for (int s = 0; s < 4; s++)
            r[s] = fmaf(-a1, W[M + s + 1], fmaf(-a2, W[M + s], cv[s]));
        *reinterpret_cast<float4*>(&B[t0]) = make_float4(r[0], r[1], r[2], r[3]);
    }
}

// pass B: A[t] = B[t] + q2c[0]*B[t-L] + q2c[1]*B[t-L+1] + q2c[2]*B[t-L+2],
// L = 2*d1+2 (even), so M in {0,2}.
template<int M>
__device__ __forceinline__ void pass_b_vec(const float* __restrict__ B,
                                           float* __restrict__ A,
                                           float c0, float c1, float c2, int d1,
                                           int tid)
{
    const int off = 2 * d1 + 2 + M;
    for (int t0 = 4 * tid; t0 < T_LEN; t0 += 4 * NT) {
        float4 c  = lds4(&B[t0]);
        float4 w0 = lds4(&B[t0 - off]);
        float4 w1 = lds4(&B[t0 - off + 4]);
        float W[8] = {w0.x, w0.y, w0.z, w0.w, w1.x, w1.y, w1.z, w1.w};
        float cv[4] = {c.x, c.y, c.z, c.w};
        float r[4];
        #pragma unroll
        for (int s = 0; s < 4; s++) {
            float p = fmaf(c1, W[M + s + 1], c2 * W[M + s + 2]);
            r[s] = fmaf(c0, W[M + s], cv[s]) + p;
        }
        *reinterpret_cast<float4*>(&A[t0]) = make_float4(r[0], r[1], r[2], r[3]);
    }
}

__global__ __launch_bounds__(NT, 1)
void ks_resonator_kernel(const float* __restrict__ x,
                         const float* __restrict__ gumbel,
                         const float* __restrict__ dparam,
                         const float* __restrict__ fgain,
                         const float* __restrict__ refl,
                         float* __restrict__ out)
{
    extern __shared__ float smem[];
    float* A = smem + PAD;                  // A[-PAD .. T_LEN)
    float* B = smem + (2 * PAD + T_LEN);    // B[-PAD .. T_LEN)

    __shared__ float red_v[NWARP];
    __shared__ int   red_i[NWARP];
    __shared__ float s_a1, s_a2;
    __shared__ int   s_d1, s_d2;

    const int tid  = threadIdx.x;
    const int lane = tid & 31;
    const int wid  = tid >> 5;
    const int row  = blockIdx.x;

    // ---- async prefetch of x row into A[0..T), two groups (halves) ----
    {
        const char* gsrc = (const char*)(x + (size_t)row * T_LEN);
        #pragma unroll
        for (int i = tid; i < T_LEN / 8; i += NT) {
            unsigned sdst = (unsigned)__cvta_generic_to_shared(A + 4 * i);
            asm volatile("cp.async.cg.shared.global [%0], [%1], 16;\n"
                         :: "r"(sdst), "l"(gsrc + 16 * (size_t)i));
        }
        asm volatile("cp.async.commit_group;\n");
        #pragma unroll
        for (int i = tid + T_LEN / 8; i < T_LEN / 4; i += NT) {
            unsigned sdst = (unsigned)__cvta_generic_to_shared(A + 4 * i);
            asm volatile("cp.async.cg.shared.global [%0], [%1], 16;\n"
                         :: "r"(sdst), "l"(gsrc + 16 * (size_t)i));
        }
        asm volatile("cp.async.commit_group;\n");
    }

    // ---- zero both pads (overlaps the cp.async fetch) ----
    {
        float4 z = make_float4(0.f, 0.f, 0.f, 0.f);
        float4* pa = reinterpret_cast<float4*>(smem);                 // A pad
        float4* pb = reinterpret_cast<float4*>(smem + PAD + T_LEN);   // B pad
        #pragma unroll
        for (int i = tid; i < PAD / 4; i += NT) { pa[i] = z; pb[i] = z; }
    }

    // ---- argmax(delay_param + gumbel) via shuffles (overlapped) ----
    {
        float v = -INFINITY;
        int   idx = 0;
        if (tid < NDELAY) { v = dparam[tid] + gumbel[tid]; idx = tid; }
        #pragma unroll
        for (int off = 16; off > 0; off >>= 1) {
            float v2 = __shfl_down_sync(0xffffffffu, v, off);
            int   i2 = __shfl_down_sync(0xffffffffu, idx, off);
            if (v2 > v || (v2 == v && i2 < idx)) { v = v2; idx = i2; }
        }
        if (lane == 0) { red_v[wid] = v; red_i[wid] = idx; }
        __syncthreads();   // also makes pad zeros visible
        if (wid == 0) {
            float vv = (lane < NWARP) ? red_v[lane] : -INFINITY;
            int   ii = (lane < NWARP) ? red_i[lane] : 0;
            #pragma unroll
            for (int off = 8; off > 0; off >>= 1) {
                float v2 = __shfl_down_sync(0xffffffffu, vv, off);
                int   i2 = __shfl_down_sync(0xffffffffu, ii, off);
                if (v2 > vv || (v2 == vv && i2 < ii)) { vv = v2; ii = i2; }
            }
            if (lane == 0) {
                int j = ii;
                float k1 = tanhf(tanhf(refl[0]));  // resonant_activation(tanh(rc), tau=0)
                float k2 = tanhf(tanhf(refl[1]));
                float a1 = k1 * (1.0f - k2);
                float a2 = fminf(fmaxf(k2, -0.999f), 0.999f);
                float a1b = 0.999f - fabsf(a2);
                a1 = fminf(fmaxf(a1, -a1b), a1b);
                float g = powf(1.0f / (1.0f + expf(-fgain[0])), 0.45f);
                s_a1 = a1 * g;
                s_a2 = a2 * g;
                s_d1 = 61 + j;
                s_d2 = 61 + ((j + 1) % NDELAY);
            }
        }
    }

    // ---- wait first half of x + coefficients ----
    asm volatile("cp.async.wait_group 1;\n");
    __syncthreads();

    const float a1 = s_a1, a2 = s_a2;
    const int d1 = s_d1, d2 = s_d2;

    // Binomial tap arrays: qNc[k] = C(N,k) a1^k a2^(N-k)
    float q2c[3], q4c[5], q8c[9];
    {
        float p1[9], p2[9];
        p1[0] = 1.f; p2[0] = 1.f;
        #pragma unroll
        for (int i = 1; i < 9; i++) { p1[i] = p1[i-1] * a1; p2[i] = p2[i-1] * a2; }
        const float C8[9] = {1.f, 8.f, 28.f, 56.f, 70.f, 56.f, 28.f, 8.f, 1.f};
        const float C4[5] = {1.f, 4.f, 6.f, 4.f, 1.f};
        #pragma unroll
        for (int k = 0; k < 9; k++) q8c[k] = C8[k] * p1[k] * p2[8 - k];
        #pragma unroll
        for (int k = 0; k < 5; k++) q4c[k] = C4[k] * p1[k] * p2[4 - k];
        q2c[0] = p2[2]; q2c[1] = 2.f * a1 * a2; q2c[2] = p1[2];
    }

    float* orow = out + (size_t)row * T_LEN;

    if (d2 == d1 + 1) {
        // ================= FAST PATH: contiguous tap windows =================
        const int mA = (4 - ((d1 + 1) & 3)) & 3;   // pass A misalignment fixup

        // pass A first half (overlaps second-half DRAM arrival)
        switch (mA) {
            case 0: pass_a_vec<0>(A, B, a1, a2, d1, 0, T_LEN / 2, tid); break;
            case 1: pass_a_vec<1>(A, B, a1, a2, d1, 0, T_LEN / 2, tid); break;
            case 2: pass_a_vec<2>(A, B, a1, a2, d1, 0, T_LEN / 2, tid); break;
            default: pass_a_vec<3>(A, B, a1, a2, d1, 0, T_LEN / 2, tid); break;
        }
        asm volatile("cp.async.wait_group 0;\n");
        __syncthreads();
        switch (mA) {
            case 0: pass_a_vec<0>(A, B, a1, a2, d1, T_LEN / 2, T_LEN, tid); break;
            case 1: pass_a_vec<1>(A, B, a1, a2, d1, T_LEN / 2, T_LEN, tid); break;
            case 2: pass_a_vec<2>(A, B, a1, a2, d1, T_LEN / 2, T_LEN, tid); break;
            default: pass_a_vec<3>(A, B, a1, a2, d1, T_LEN / 2, T_LEN, tid); break;
        }
        __syncthreads();

        // pass B: A = (1 + q^2) B ; L = 2d1+2 is even -> fixup in {0,2}
        if (((2 * d1 + 2) & 3) == 0)
            pass_b_vec<0>(B, A, q2c[0], q2c[1], q2c[2], d1, tid);
        else
            pass_b_vec<2>(B, A, q2c[0], q2c[1], q2c[2], d1, tid);
        __syncthreads();

        // pass C: B = (1 + q^4) A ; window base t0-(4d1+4) is aligned
        {
            const int L = 4 * d1 + 4;
            #pragma unroll 4
            for (int t0 = 4 * tid; t0 < T_LEN; t0 += 4 * NT) {
                float4 cv = lds4(&A[t0]);
                float4 w0 = lds4(&A[t0 - L]);
                float4 w1 = lds4(&A[t0 - L + 4]);
                float W[8] = {w0.x, w0.y, w0.z, w0.w, w1.x, w1.y, w1.z, w1.w};
                float Cn[4] = {cv.x, cv.y, cv.z, cv.w};
                float acc[4];
                #pragma unroll
                for (int s = 0; s < 4; s++) {
                    float u0 = fmaf(q4c[0], W[s],     Cn[s]);
                    float u1 = fmaf(q4c[1], W[s + 1], q4c[2] * W[s + 2]);
                    float u2 = fmaf(q4c[3], W[s + 3], q4c[4] * W[s + 4]);
                    acc[s] = u0 + (u1 + u2);
                }
                *reinterpret_cast<float4*>(&B[t0]) =
                    make_float4(acc[0], acc[1], acc[2], acc[3]);
            }
        }
        __syncthreads();

        // recurrence: y = B + q^8 y in place; only warps with work participate.
        {
            const int L  = 8 * d1 + 8;
            const int Cq = 8 * d1;                       // chunk (mult of 4)
            const int nw_act = min(NWARP, (2 * d1 + 31) >> 5);
            const int nthr   = nw_act * 32;
            if (wid < nw_act) {
                for (int base = 0; base < T_LEN; base += Cq) {
                    const int end = min(base + Cq, T_LEN);
                    for (int t0 = base + 4 * tid; t0 < end; t0 += 4 * nthr) {
                        float4 cv = lds4(&B[t0]);
                        float4 w0 = lds4(&B[t0 - L]);
                        float4 w1 = lds4(&B[t0 - L + 4]);
                        float4 w2 = lds4(&B[t0 - L + 8]);
                        float W[12] = {w0.x, w0.y, w0.z, w0.w,
                                       w1.x, w1.y, w1.z, w1.w,
                                       w2.x, w2.y, w2.z, w2.w};
                        float Cn[4] = {cv.x, cv.y, cv.z, cv.w};
                        float acc[4];
                        #pragma unroll
                        for (int s = 0; s < 4; s++) {
                            float u0 = fmaf(q8c[0], W[s],     Cn[s]);
                            float u1 = fmaf(q8c[1], W[s + 1], q8c[2] * W[s + 2]);
                            float u2 = fmaf(q8c[3], W[s + 3], q8c[4] * W[s + 4]);
                            float u3 = fmaf(q8c[5], W[s + 5], q8c[6] * W[s + 6]);
                            float u4 = fmaf(q8c[7], W[s + 7], q8c[8] * W[s + 8]);
                            acc[s] = (u0 + u1) + ((u2 + u3) + u4);
                        }
                        float4 r = make_float4(acc[0], acc[1], acc[2], acc[3]);
                        *reinterpret_cast<float4*>(&B[t0]) = r;
                        *reinterpret_cast<float4*>(&orow[t0]) = r;  // fused STG
                    }
                    if (base + Cq < T_LEN)   // no barrier after final chunk
                        asm volatile("bar.sync 1, %0;\n" :: "r"(nthr) : "memory");
                }
            }
            // warps >= nw_act: nothing left to do, fall through to exit
        }
    } else {
        // ================= GENERIC PATH (j == 359): scalar =================
        const int l20 = 2 * d1, l21 = d1 + d2, l22 = 2 * d2;
        int l4[5], lg[9];
        #pragma unroll
        for (int i = 0; i < 5; i++) l4[i] = i * d1 + (4 - i) * d2;
        #pragma unroll
        for (int i = 0; i < 9; i++) lg[i] = i * d1 + (8 - i) * d2;
        const int Cq = 8 * min(d1, d2);

        asm volatile("cp.async.wait_group 0;\n");
        __syncthreads();

        #pragma unroll 4
        for (int t = tid; t < T_LEN; t += NT)
            B[t] = fmaf(-a1, A[t - d1], fmaf(-a2, A[t - d2], A[t]));
        __syncthreads();

        #pragma unroll 4
        for (int t = tid; t < T_LEN; t += NT)
            A[t] = fmaf(q2c[2], B[t - l20],
                   fmaf(q2c[1], B[t - l21],
                   fmaf(q2c[0], B[t - l22], B[t])));
        __syncthreads();

        #pragma unroll 4
        for (int t = tid; t < T_LEN; t += NT) {
            float acc = A[t];
            #pragma unroll
            for (int i = 0; i < 5; i++) acc = fmaf(q4c[i], A[t - l4[i]], acc);
            B[t] = acc;
        }
        __syncthreads();

        for (int base = 0; base < T_LEN; base += Cq) {
            const int end = min(base + Cq, T_LEN);
            for (int t = base + tid; t < end; t += NT) {
                float acc = B[t];
                #pragma unroll
                for (int i = 0; i < 9; i++) acc = fmaf(q8c[i], B[t - lg[i]], acc);
                B[t] = acc;
                orow[t] = acc;
            }
            __syncthreads();
        }
    }
}

extern "C" void kernel_launch(void* const* d_in, const int* in_sizes, int n_in,
                              void* d_out, int out_size)
{
    const float* excitation = (const float*)d_in[0];  // (128,1,8192)
    const float* gumbel     = (const float*)d_in[1];  // (360,)
    const float* dparam     = (const float*)d_in[2];  // (360,)
    const float* fgain      = (const float*)d_in[3];  // (1,)
    const float* refl       = (const float*)d_in[4];  // (2,)
    float* out = (float*)d_out;                       // (128,1,8192)

    const int smem_bytes = (2 * (T_LEN + PAD)) * sizeof(float); // ~92.4 KB
    cudaFuncSetAttribute(ks_resonator_kernel,
                         cudaFuncAttributeMaxDynamicSharedMemorySize, smem_bytes);

    ks_resonator_kernel<<<B_ROWS, NT, smem_bytes>>>(
        excitation, gumbel, dparam, fgain, refl, out);
}

// round 15
// speedup vs baseline: 1.2226x; 1.2226x over previous
#include <cuda_runtime.h>
#include <math.h>

// KarplusStrongResonator: (1 + q) Y = X, q = a1 z^-d1 + a2 z^-d2,
// d1 = 61 + argmax(delay_param + gumbel), d2 = 61 + ((argmax+1) % 360).
// Identity: (1 - q^8) Y = (1-q)(1+q^2)(1+q^4) X.
// Fast path (d2 == d1+1):
//   phase 1:  B = (1 - q + q^2 - q^3) X        (one fused parallel pass)
//   phase 2:  y = (1+q^4)B + q^8 y  per chunk  (pass C fused into recurrence)
// All windows are contiguous; q^4/q^8 windows are 4-aligned; the fused pass's
// three windows share alignment residue r = (d1+1)&3 (template-dispatched).

#define T_LEN 8192
#define B_ROWS 128
#define NDELAY 360
#define NT 512
#define NWARP (NT / 32)
#define PAD 3360   // == 8*419 + 8 (max q^8 lag), multiple of 4

__device__ __forceinline__ float4 lds4(const float* p) {
    return *reinterpret_cast<const float4*>(p);
}

// Fused pass: B[t] = A[t] - q A + q^2 A - q^3 A.
// Group k (k=1..3) taps: coeff sgn_k*C(k,i)*a1^i*a2^(k-i) at lag k*d1+k-i.
// Window W_k[j] = A[t0 - off_k + j], off_k = k*(d1+1) + M_k, M_k = (4-(k*R&3))&3.
template<int R>
__device__ __forceinline__ void fused_pass(const float* __restrict__ A,
                                           float* __restrict__ B,
                                           float a1, float a2, int d1,
                                           int t_begin, int t_end, int tid)
{
    constexpr int M1 = (4 - (R & 3)) & 3;
    constexpr int M2 = (4 - ((2 * R) & 3)) & 3;
    constexpr int M3 = (4 - ((3 * R) & 3)) & 3;
    constexpr int NV1 = (M1 + 1 + 4 + 3) / 4;   // float4 loads per window
    constexpr int NV2 = (M2 + 2 + 4 + 3) / 4;
    constexpr int NV3 = (M3 + 3 + 4 + 3) / 4;
    const int off1 = (d1 + 1) + M1;
    const int off2 = 2 * (d1 + 1) + M2;
    const int off3 = 3 * (d1 + 1) + M3;

    // tap coefficients (signs folded in: -q, +q^2, -q^3)
    const float c10 = -a2,            c11 = -a1;
    const float c20 =  a2 * a2,       c21 = 2.f * a1 * a2,  c22 = a1 * a1;
    const float c30 = -a2 * a2 * a2,  c31 = -3.f * a1 * a2 * a2,
                c32 = -3.f * a1 * a1 * a2, c33 = -a1 * a1 * a1;

    for (int t0 = t_begin + 4 * tid; t0 < t_end; t0 += 4 * NT) {
        float4 c = lds4(&A[t0]);
        float W1[NV1 * 4], W2[NV2 * 4], W3[NV3 * 4];
        #pragma unroll
        for (int v = 0; v < NV1; v++) {
            float4 w = lds4(&A[t0 - off1 + 4 * v]);
            W1[4*v] = w.x; W1[4*v+1] = w.y; W1[4*v+2] = w.z; W1[4*v+3] = w.w;
        }
        #pragma unroll
        for (int v = 0; v < NV2; v++) {
            float4 w = lds4(&A[t0 - off2 + 4 * v]);
            W2[4*v] = w.x; W2[4*v+1] = w.y; W2[4*v+2] = w.z; W2[4*v+3] = w.w;
        }
        #pragma unroll
        for (int v = 0; v < NV3; v++) {
            float4 w = lds4(&A[t0 - off3 + 4 * v]);
            W3[4*v] = w.x; W3[4*v+1] = w.y; W3[4*v+2] = w.z; W3[4*v+3] = w.w;
        }
        float cv[4] = {c.x, c.y, c.z, c.w};
        float r[4];
        #pragma unroll
        for (int s = 0; s < 4; s++) {
            float v0 = fmaf(c10, W1[M1 + s],     cv[s]);
            float v1 = fmaf(c11, W1[M1 + s + 1], c20 * W2[M2 + s]);
            float v2 = fmaf(c21, W2[M2 + s + 1], c22 * W2[M2 + s + 2]);
            float v3 = fmaf(c30, W3[M3 + s],     c31 * W3[M3 + s + 1]);
            float v4 = fmaf(c32, W3[M3 + s + 2], c33 * W3[M3 + s + 3]);
            r[s] = (v0 + v1) + (v2 + (v3 + v4));
        }
        *reinterpret_cast<float4*>(&B[t0]) = make_float4(r[0], r[1], r[2], r[3]);
    }
}

__global__ __launch_bounds__(NT, 1)
void ks_resonator_kernel(const float* __restrict__ x,
                         const float* __restrict__ gumbel,
                         const float* __restrict__ dparam,
                         const float* __restrict__ fgain,
                         const float* __restrict__ refl,
                         float* __restrict__ out)
{
    extern __shared__ float smem[];
    float* A = smem + PAD;                  // A[-PAD .. T_LEN): x, then y
    float* B = smem + (2 * PAD + T_LEN);    // B[-PAD .. T_LEN): fused-pass out

    __shared__ float red_v[NWARP];
    __shared__ int   red_i[NWARP];
    __shared__ float s_a1, s_a2;
    __shared__ int   s_d1, s_d2;

    const int tid  = threadIdx.x;
    const int lane = tid & 31;
    const int wid  = tid >> 5;
    const int row  = blockIdx.x;

    // ---- async prefetch of x row into A[0..T), two groups (halves) ----
    {
        const char* gsrc = (const char*)(x + (size_t)row * T_LEN);
        #pragma unroll
        for (int i = tid; i < T_LEN / 8; i += NT) {
            unsigned sdst = (unsigned)__cvta_generic_to_shared(A + 4 * i);
            asm volatile("cp.async.cg.shared.global [%0], [%1], 16;\n"
                         :: "r"(sdst), "l"(gsrc + 16 * (size_t)i));
        }
        asm volatile("cp.async.commit_group;\n");
        #pragma unroll
        for (int i = tid + T_LEN / 8; i < T_LEN / 4; i += NT) {
            unsigned sdst = (unsigned)__cvta_generic_to_shared(A + 4 * i);
            asm volatile("cp.async.cg.shared.global [%0], [%1], 16;\n"
                         :: "r"(sdst), "l"(gsrc + 16 * (size_t)i));
        }
        asm volatile("cp.async.commit_group;\n");
    }

    // ---- zero both pads (overlaps the cp.async fetch) ----
    {
        float4 z = make_float4(0.f, 0.f, 0.f, 0.f);
        float4* pa = reinterpret_cast<float4*>(smem);                 // A pad
        float4* pb = reinterpret_cast<float4*>(smem + PAD + T_LEN);   // B pad
        #pragma unroll
        for (int i = tid; i < PAD / 4; i += NT) { pa[i] = z; pb[i] = z; }
    }

    // ---- argmax(delay_param + gumbel) via shuffles (overlapped) ----
    {
        float v = -INFINITY;
        int   idx = 0;
        if (tid < NDELAY) { v = dparam[tid] + gumbel[tid]; idx = tid; }
        #pragma unroll
        for (int off = 16; off > 0; off >>= 1) {
            float v2 = __shfl_down_sync(0xffffffffu, v, off);
            int   i2 = __shfl_down_sync(0xffffffffu, idx, off);
            if (v2 > v || (v2 == v && i2 < idx)) { v = v2; idx = i2; }
        }
        if (lane == 0) { red_v[wid] = v; red_i[wid] = idx; }
        __syncthreads();   // also makes pad zeros visible
        if (wid == 0) {
            float vv = (lane < NWARP) ? red_v[lane] : -INFINITY;
            int   ii = (lane < NWARP) ? red_i[lane] : 0;
            #pragma unroll
            for (int off = 8; off > 0; off >>= 1) {
                float v2 = __shfl_down_sync(0xffffffffu, vv, off);
                int   i2 = __shfl_down_sync(0xffffffffu, ii, off);
                if (v2 > vv || (v2 == vv && i2 < ii)) { vv = v2; ii = i2; }
            }
            if (lane == 0) {
                int j = ii;
                float k1 = tanhf(tanhf(refl[0]));  // resonant_activation(tanh(rc), tau=0)
                float k2 = tanhf(tanhf(refl[1]));
                float a1 = k1 * (1.0f - k2);
                float a2 = fminf(fmaxf(k2, -0.999f), 0.999f);
                float a1b = 0.999f - fabsf(a2);
                a1 = fminf(fmaxf(a1, -a1b), a1b);
                float g = powf(1.0f / (1.0f + expf(-fgain[0])), 0.45f);
                s_a1 = a1 * g;
                s_a2 = a2 * g;
                s_d1 = 61 + j;
                s_d2 = 61 + ((j + 1) % NDELAY);
            }
        }
    }

    // ---- wait first half of x + coefficients ----
    asm volatile("cp.async.wait_group 1;\n");
    __syncthreads();

    const float a1 = s_a1, a2 = s_a2;
    const int d1 = s_d1, d2 = s_d2;

    // q^4, q^8 tap arrays: qNc[k] = C(N,k) a1^k a2^(N-k) at lag N*d1+N-k
    float q4c[5], q8c[9];
    {
        float p1[9], p2[9];
        p1[0] = 1.f; p2[0] = 1.f;
        #pragma unroll
        for (int i = 1; i < 9; i++) { p1[i] = p1[i-1] * a1; p2[i] = p2[i-1] * a2; }
        const float C8[9] = {1.f, 8.f, 28.f, 56.f, 70.f, 56.f, 28.f, 8.f, 1.f};
        const float C4[5] = {1.f, 4.f, 6.f, 4.f, 1.f};
        #pragma unroll
        for (int k = 0; k < 9; k++) q8c[k] = C8[k] * p1[k] * p2[8 - k];
        #pragma unroll
        for (int k = 0; k < 5; k++) q4c[k] = C4[k] * p1[k] * p2[4 - k];
    }

    float* orow = out + (size_t)row * T_LEN;

    if (d2 == d1 + 1) {
        // ================= FAST PATH =================
        const int R = (d1 + 1) & 3;

        // fused pass, first half (overlaps second-half DRAM arrival)
        switch (R) {
            case 0: fused_pass<0>(A, B, a1, a2, d1, 0, T_LEN/2, tid); break;
            case 1: fused_pass<1>(A, B, a1, a2, d1, 0, T_LEN/2, tid); break;
            case 2: fused_pass<2>(A, B, a1, a2, d1, 0, T_LEN/2, tid); break;
            default: fused_pass<3>(A, B, a1, a2, d1, 0, T_LEN/2, tid); break;
        }
        asm volatile("cp.async.wait_group 0;\n");
        __syncthreads();
        switch (R) {
            case 0: fused_pass<0>(A, B, a1, a2, d1, T_LEN/2, T_LEN, tid); break;
            case 1: fused_pass<1>(A, B, a1, a2, d1, T_LEN/2, T_LEN, tid); break;
            case 2: fused_pass<2>(A, B, a1, a2, d1, T_LEN/2, T_LEN, tid); break;
            default: fused_pass<3>(A, B, a1, a2, d1, T_LEN/2, T_LEN, tid); break;
        }
        __syncthreads();

        // recurrence with fused (1+q^4):  y[t] = B[t] + q^4*B + q^8*y
        // y written over A (x is fully consumed by the fused pass).
        // q^4 window at off4 = 4d1+4 (aligned), q^8 window at off8 = 8d1+8.
        {
            const int off4 = 4 * d1 + 4;
            const int off8 = 8 * d1 + 8;
            const int Cq   = 8 * d1;                     // chunk (mult of 4)
            const int nw_act = min(NWARP, (d1 + 15) >> 4);
            const int nthr   = nw_act * 32;
            if (wid < nw_act) {
                for (int base = 0; base < T_LEN; base += Cq) {
                    const int end = min(base + Cq, T_LEN);
                    for (int t0 = base + 4 * tid; t0 < end; t0 += 4 * nthr) {
                        float4 cv = lds4(&B[t0]);
                        float4 b0 = lds4(&B[t0 - off4]);
                        float4 b1 = lds4(&B[t0 - off4 + 4]);
                        float4 y0 = lds4(&A[t0 - off8]);
                        float4 y1 = lds4(&A[t0 - off8 + 4]);
                        float4 y2 = lds4(&A[t0 - off8 + 8]);
                        float W4[8]  = {b0.x, b0.y, b0.z, b0.w,
                                        b1.x, b1.y, b1.z, b1.w};
                        float W8[12] = {y0.x, y0.y, y0.z, y0.w,
                                        y1.x, y1.y, y1.z, y1.w,
                                        y2.x, y2.y, y2.z, y2.w};
                        float Cn[4] = {cv.x, cv.y, cv.z, cv.w};
                        float acc[4];
                        #pragma unroll
                        for (int s = 0; s < 4; s++) {
                            float u0 = fmaf(q4c[0], W4[s],     Cn[s]);
                            float u1 = fmaf(q4c[1], W4[s + 1], q4c[2] * W4[s + 2]);
                            float u2 = fmaf(q4c[3], W4[s + 3], q4c[4] * W4[s + 4]);
                            float u3 = fmaf(q8c[0], W8[s],     q8c[1] * W8[s + 1]);
                            float u4 = fmaf(q8c[2], W8[s + 2], q8c[3] * W8[s + 3]);
                            float u5 = fmaf(q8c[4], W8[s + 4], q8c[5] * W8[s + 5]);
                            float u6 = fmaf(q8c[6], W8[s + 6], q8c[7] * W8[s + 7]);
                            float u7 = q8c[8] * W8[s + 8];
                            acc[s] = ((u0 + u1) + (u2 + u3))
                                   + ((u4 + u5) + (u6 + u7));
                        }
                        float4 r = make_float4(acc[0], acc[1], acc[2], acc[3]);
                        *reinterpret_cast<float4*>(&A[t0]) = r;
                        *reinterpret_cast<float4*>(&orow[t0]) = r;  // fused STG
                    }
                    if (base + Cq < T_LEN)   // no barrier after final chunk
                        asm volatile("bar.sync 1, %0;\n" :: "r"(nthr) : "memory");
                }
            }
            // inactive warps fall through to exit
        }
    } else {
        // ================= GENERIC PATH (j == 359): scalar =================
        float q2g[3];
        q2g[0] = a2 * a2; q2g[1] = 2.f * a1 * a2; q2g[2] = a1 * a1;
        const int l20 = 2 * d1, l21 = d1 + d2, l22 = 2 * d2;
        int l4[5], lg[9];
        #pragma unroll
        for (int i = 0; i < 5; i++) l4[i] = i * d1 + (4 - i) * d2;
        #pragma unroll
        for (int i = 0; i < 9; i++) lg[i] = i * d1 + (8 - i) * d2;
        const int Cq = 8 * min(d1, d2);

        asm volatile("cp.async.wait_group 0;\n");
        __syncthreads();

        #pragma unroll 4
        for (int t = tid; t < T_LEN; t += NT)
            B[t] = fmaf(-a1, A[t - d1], fmaf(-a2, A[t - d2], A[t]));
        __syncthreads();

        #pragma unroll 4
        for (int t = tid; t < T_LEN; t += NT)
            A[t] = fmaf(q2g[2], B[t - l20],
                   fmaf(q2g[1], B[t - l21],
                   fmaf(q2g[0], B[t - l22], B[t])));
        __syncthreads();

        #pragma unroll 4
        for (int t = tid; t < T_LEN; t += NT) {
            float acc = A[t];
            #pragma unroll
            for (int i = 0; i < 5; i++) acc = fmaf(q4c[i], A[t - l4[i]], acc);
            B[t] = acc;
        }
        __syncthreads();

        for (int base = 0; base < T_LEN; base += Cq) {
            const int end = min(base + Cq, T_LEN);
            for (int t = base + tid; t < end; t += NT) {
                float acc = B[t];
                #pragma unroll
                for (int i = 0; i < 9; i++) acc = fmaf(q8c[i], B[t - lg[i]], acc);
                B[t] = acc;
                orow[t] = acc;
            }
            __syncthreads();
        }
    }
}

extern "C" void kernel_launch(void* const* d_in, const int* in_sizes, int n_in,
                              void* d_out, int out_size)
{
    const float* excitation = (const float*)d_in[0];  // (128,1,8192)
    const float* gumbel     = (const float*)d_in[1];  // (360,)
    const float* dparam     = (const float*)d_in[2];  // (360,)
    const float* fgain      = (const float*)d_in[3];  // (1,)
    const float* refl       = (const float*)d_in[4];  // (2,)
    float* out = (float*)d_out;                       // (128,1,8192)

    const int smem_bytes = (2 * (T_LEN + PAD)) * sizeof(float); // ~92.4 KB
    cudaFuncSetAttribute(ks_resonator_kernel,
                         cudaFuncAttributeMaxDynamicSharedMemorySize, smem_bytes);

    ks_resonator_kernel<<<B_ROWS, NT, smem_bytes>>>(
        excitation, gumbel, dparam, fgain, refl, out);
}